// round 13
// baseline (speedup 1.0000x reference)
#include <cuda_runtime.h>
#include <math.h>

// Problem constants
#define WINDOW 40
#define E 8
#define FDIM 64
#define TDIM 64
#define KERNEL 5
#define IN_CH 144          // F + 10*E
#define LIN_IN 36          // WINDOW + 1 - KERNEL
#define NCOL 320           // WINDOW * E rank columns
#define NMAX 8192

// Scratch (device globals — no allocation allowed)
__device__ float g_cols[(size_t)NCOL * NMAX];   // [col][n] gathered last-window values
__device__ float g_rankT[(size_t)NCOL * NMAX];  // [col][n] rank/N (coalesced writes)
__device__ float g_rank[(size_t)NMAX * NCOL];   // [n][col] rank/N (coalesced main reads)

// ---------------------------------------------------------------------------
// Kernel 1: gather x[:, 24+t, 0:8] -> g_cols[(t*8+f)][n]  (proven ~12us)
// ---------------------------------------------------------------------------
__global__ void gather_kernel(const float* __restrict__ x, int N) {
    __shared__ float tile[256][9];   // pad 9 -> conflict-free both phases
    const int t  = blockIdx.y;
    const int n0 = blockIdx.x * 256;
    const int tid = threadIdx.x;
    const int n = n0 + tid;
    if (n < N) {
        const float4* p = (const float4*)(x + (size_t)n * (TDIM * FDIM) + (24 + t) * FDIM);
        float4 a = p[0], b = p[1];
        tile[tid][0] = a.x; tile[tid][1] = a.y; tile[tid][2] = a.z; tile[tid][3] = a.w;
        tile[tid][4] = b.x; tile[tid][5] = b.y; tile[tid][6] = b.z; tile[tid][7] = b.w;
    }
    __syncthreads();
    #pragma unroll
    for (int idx = tid; idx < 8 * 256; idx += 256) {
        int f = idx >> 8, s = idx & 255;
        int nn = n0 + s;
        if (nn < N) g_cols[(size_t)(t * 8 + f) * NMAX + nn] = tile[s][f];
    }
}

// ---------------------------------------------------------------------------
// Kernel 2: exact stable descending rank (R3/R7-proven algorithm).
// ONLY change vs R11: padded hist layout -> bijective interleaved layout
//   phys(L) = (L&31)*512 + (L>>5)
// (scan ownership tid*32+w maps to phys w*512+tid: stride-512, conflict-free,
//  ZERO padding). smem 116736 -> 114688 B  => 2 blocks/SM instead of 1.
// ---------------------------------------------------------------------------
#define RT 512
#define NBIN 32768                 // 15-bit buckets of the ascending key
#define HWORDS (NBIN / 2)          // 16384 packed u16-pair words
__device__ __forceinline__ int hphys(unsigned int L) {
    return (int)(((L & 31u) << 9) | (L >> 5));   // bijection on [0,16384)
}

// dynamic smem: keys u32[8192] | hist u32[HWORDS] | order u16[8192] = 114688 B
#define OFF_HIST 32768
#define OFF_ORD  (OFF_HIST + HWORDS * 4)
#define RANK_SMEM (OFF_ORD + NMAX * 2)

__global__ __launch_bounds__(RT) void rank_kernel(int N) {
    extern __shared__ unsigned char sm_raw[];
    unsigned int*   keys  = (unsigned int*)sm_raw;
    unsigned int*   hist  = (unsigned int*)(sm_raw + OFF_HIST);
    unsigned short* order = (unsigned short*)(sm_raw + OFF_ORD);
    __shared__ unsigned int aux2[16];

    const int c    = blockIdx.x;
    const int tid  = threadIdx.x;
    const int lane = tid & 31, wrp = tid >> 5;

    for (int i = tid; i < HWORDS; i += RT) hist[i] = 0u;
    __syncthreads();

    // load keys (coalesced from g_cols) + histogram
    const float* col = &g_cols[(size_t)c * NMAX];
    for (int i = tid; i < N; i += RT) {
        unsigned int u = __float_as_uint(col[i]);
        unsigned int mono = u ^ ((u >> 31) ? 0xFFFFFFFFu : 0x80000000u);
        unsigned int k = ~mono;                 // ascending k == descending value
        keys[i] = k;
        unsigned int b = k >> 17;               // top 15 bits
        atomicAdd(&hist[hphys(b >> 1)], 1u << ((b & 1) * 16));
    }
    __syncthreads();

    // exclusive scan over 32768 bins; thread owns logical words tid*32..+31,
    // physical w*512+tid -> conflict-free, no padding
    unsigned int tsum = 0;
    #pragma unroll
    for (int w = 0; w < 32; ++w) {
        unsigned int v = hist[w * 512 + tid];
        tsum += (v & 0xFFFFu) + (v >> 16);
    }
    unsigned int v = tsum;
    #pragma unroll
    for (int d = 1; d < 32; d <<= 1) {
        unsigned int t2 = __shfl_up_sync(0xFFFFFFFFu, v, d);
        if (lane >= d) v += t2;
    }
    if (lane == 31) aux2[wrp] = v;
    __syncthreads();
    if (wrp == 0 && lane < 16) {
        unsigned int s = aux2[lane];
        #pragma unroll
        for (int d = 1; d < 16; d <<= 1) {
            unsigned int t2 = __shfl_up_sync(0x0000FFFFu, s, d);
            if (lane >= d) s += t2;
        }
        aux2[lane] = s;
    }
    __syncthreads();
    unsigned int run = v - tsum + (wrp ? aux2[wrp - 1] : 0u);  // exclusive prefix
    #pragma unroll
    for (int w = 0; w < 32; ++w) {
        unsigned int pv = hist[w * 512 + tid];
        unsigned int lo = pv & 0xFFFFu, hi = pv >> 16;
        hist[w * 512 + tid] = run | ((run + lo) << 16);   // packed bucket-start cursors
        run += lo + hi;
    }
    __syncthreads();

    // scatter element indices into bucket-grouped order[]
    for (int i = tid; i < N; i += RT) {
        unsigned int b = keys[i] >> 17;
        unsigned int sh = (b & 1) * 16;
        unsigned int old = atomicAdd(&hist[hphys(b >> 1)], 1u << sh);
        order[(old >> sh) & 0xFFFFu] = (unsigned short)i;
    }
    __syncthreads();
    // cursors now hold bucket ENDS: end(b) = start(b+1)

    // exact rank: start-of-bucket + within-bucket compares (key, then index)
    const float inv = 1.0f / (float)N;
    float* dst = &g_rankT[(size_t)c * NMAX];
    for (int i = tid; i < N; i += RT) {
        unsigned int k = keys[i];
        unsigned int b = k >> 17;
        unsigned int we = hist[hphys(b >> 1)];
        int e = (we >> ((b & 1) * 16)) & 0xFFFF;
        int s = 0;
        if (b) {
            unsigned int b1 = b - 1;
            unsigned int ws2 = hist[hphys(b1 >> 1)];
            s = (ws2 >> ((b1 & 1) * 16)) & 0xFFFF;
        }
        int r = s;
        for (int p = s; p < e; ++p) {
            int j = order[p];
            unsigned int kj = keys[j];
            r += (kj < k) || (kj == k && j < i);
        }
        dst[i] = (float)r * inv;        // coalesced store
    }
}

// ---------------------------------------------------------------------------
// Kernel 3: transpose g_rankT[c][n] -> g_rank[n][c] (both sides coalesced)
// ---------------------------------------------------------------------------
__global__ void transpose_kernel(int N) {
    __shared__ float tile[32][33];
    const int c0 = blockIdx.x * 32;
    const int n0 = blockIdx.y * 32;
    const int tx = threadIdx.x, ty = threadIdx.y;   // 32 x 8
    #pragma unroll
    for (int j = ty; j < 32; j += 8) {
        int n = n0 + tx;
        if (n < N) tile[j][tx] = g_rankT[(size_t)(c0 + j) * NMAX + n];
    }
    __syncthreads();
    #pragma unroll
    for (int j = ty; j < 32; j += 8) {
        int n = n0 + j;
        if (n < N) g_rank[(size_t)n * NCOL + c0 + tx] = tile[tx][j];
    }
}

// ---------------------------------------------------------------------------
// Kernel 4: per-sample stats + channel-127 conv + leaky + linear.
// (R11-proven: __launch_bounds__(320,5), regs 32, occ 82%)
// ---------------------------------------------------------------------------
__global__ __launch_bounds__(320, 5) void main_kernel(
    const float* __restrict__ x, const float* __restrict__ conv_w,
    const float* __restrict__ conv_b, const float* __restrict__ lin_w,
    const float* __restrict__ lin_b, float* __restrict__ out, int N)
{
    __shared__ float xe[59 * 8];          // rows 5..63 of first 8 features
    __shared__ float xc[WINDOW * IN_CH];  // assembled conv input [40][144]
    __shared__ float ws[IN_CH * KERNEL];  // conv_w[127]
    __shared__ float lw[LIN_IN];
    __shared__ float part[LIN_IN];
    __shared__ float part2[36 * 37];      // [t][chunk j], padded stride 37

    const int n   = blockIdx.x;
    const int tid = threadIdx.x;
    const float* xn = x + (size_t)n * (TDIM * FDIM);

    // ---- phase 1: loads ----
    for (int i = tid; i < IN_CH * KERNEL; i += 320) ws[i] = conv_w[127 * IN_CH * KERNEL + i];
    if (tid < LIN_IN) lw[tid] = lin_w[tid];

    for (int i = tid; i < 59 * 8; i += 320) {
        int r = i >> 3, f = i & 7;
        xe[i] = xn[(5 + r) * FDIM + f];
    }
    {   // raw channels: x[n, 24:64, 0:64] is 2560 contiguous floats
        const float4* src = (const float4*)(xn + 24 * FDIM);
        for (int q = tid; q < 640; q += 320) {
            float4 v = src[q];
            int l = q * 4;
            int t = l >> 6, i = l & 63;
            *(float4*)&xc[t * IN_CH + i] = v;
        }
    }
    {   // rank: coalesced 1280B block read; feeds week (80..87) and month (120..127)
        float r = __ldg(&g_rank[(size_t)n * NCOL + tid]);
        int t = tid >> 3, f = tid & 7;
        xc[t * IN_CH + 80 + f]  = r;
        xc[t * IN_CH + 120 + f] = r;
    }
    __syncthreads();

    // ---- phase 2: sliding-window stats (thread = one (t,f) pair) ----
    {
        const int t = tid >> 3, f = tid & 7;
        float* row = &xc[t * IN_CH];
        float s = 0.f, s2 = 0.f, mx = -1e30f, mn = 1e30f;
        #pragma unroll
        for (int j = 0; j < 5; ++j) {
            float v = xe[(15 + t + j) * 8 + f];
            s += v; s2 = fmaf(v, v, s2);
            mx = fmaxf(mx, v); mn = fminf(mn, v);
        }
        row[64 + f] = s * 0.2f;
        row[72 + f] = sqrtf(fmaxf((s2 - s * s * 0.2f) * 0.25f, 0.f));
        row[88 + f] = mx;
        row[96 + f] = mn;
        s = 0.f; s2 = 0.f; mx = -1e30f; mn = 1e30f;
        #pragma unroll
        for (int j = 0; j < 20; ++j) {
            float v = xe[(t + j) * 8 + f];
            s += v; s2 = fmaf(v, v, s2);
            mx = fmaxf(mx, v); mn = fminf(mn, v);
        }
        row[104 + f] = s * 0.05f;
        row[112 + f] = sqrtf(fmaxf((s2 - s * s * 0.05f) * (1.0f / 19.0f), 0.f));
        row[128 + f] = mx;
        row[136 + f] = mn;
    }
    __syncthreads();

    // ---- phase 3: conv ch-127 via sliding accumulation ----
    // 144 threads: q = t-range quarter (9 outputs), j = float4 channel chunk.
    if (tid < 144) {
        const int q = tid / 36, j = tid - q * 36;
        float4 w4[KERNEL];
        #pragma unroll
        for (int k = 0; k < KERNEL; ++k) {
            w4[k].x = ws[(4 * j + 0) * KERNEL + k];
            w4[k].y = ws[(4 * j + 1) * KERNEL + k];
            w4[k].z = ws[(4 * j + 2) * KERNEL + k];
            w4[k].w = ws[(4 * j + 3) * KERNEL + k];
        }
        float acc[9];
        #pragma unroll
        for (int a = 0; a < 9; ++a) acc[a] = 0.f;
        const float4* xc4 = (const float4*)xc;
        const int r0 = 9 * q;
        #pragma unroll
        for (int rr = 0; rr < 13; ++rr) {
            float4 vv = xc4[(r0 + rr) * 36 + j];
            #pragma unroll
            for (int k = 0; k < KERNEL; ++k) {
                const int tt = rr - k;
                if (tt >= 0 && tt <= 8) {
                    acc[tt] = fmaf(w4[k].x, vv.x, acc[tt]);
                    acc[tt] = fmaf(w4[k].y, vv.y, acc[tt]);
                    acc[tt] = fmaf(w4[k].z, vv.z, acc[tt]);
                    acc[tt] = fmaf(w4[k].w, vv.w, acc[tt]);
                }
            }
        }
        #pragma unroll
        for (int a = 0; a < 9; ++a) part2[(r0 + a) * 37 + j] = acc[a];
    }
    __syncthreads();

    if (tid < LIN_IN) {
        float s = 0.f;
        #pragma unroll
        for (int j2 = 0; j2 < 36; ++j2) s += part2[tid * 37 + j2];
        s += conv_b[127];
        s = (s >= 0.0f) ? s : 0.01f * s;   // leaky ALPHA=0.01
        part[tid] = s * lw[tid];
    }
    __syncthreads();
    if (tid < 32) {
        float v = part[tid] + ((tid < 4) ? part[32 + tid] : 0.0f);
        #pragma unroll
        for (int d = 16; d > 0; d >>= 1)
            v += __shfl_down_sync(0xFFFFFFFFu, v, d);
        if (tid == 0) out[n] = v + lin_b[0];
    }
}

// ---------------------------------------------------------------------------
extern "C" void kernel_launch(void* const* d_in, const int* in_sizes, int n_in,
                              void* d_out, int out_size) {
    const float* x      = (const float*)d_in[0];
    const float* conv_w = (const float*)d_in[1];
    const float* conv_b = (const float*)d_in[2];
    const float* lin_w  = (const float*)d_in[3];
    const float* lin_b  = (const float*)d_in[4];
    float* out = (float*)d_out;
    const int N = in_sizes[0] / (TDIM * FDIM);   // 8000

    cudaFuncSetAttribute(rank_kernel, cudaFuncAttributeMaxDynamicSharedMemorySize, RANK_SMEM);

    dim3 gg((N + 255) / 256, WINDOW);
    gather_kernel<<<gg, 256>>>(x, N);
    rank_kernel<<<NCOL, RT, RANK_SMEM>>>(N);
    dim3 tb(32, 8);
    dim3 tg(NCOL / 32, (N + 31) / 32);
    transpose_kernel<<<tg, tb>>>(N);
    main_kernel<<<N, 320>>>(x, conv_w, conv_b, lin_w, lin_b, out, N);
}

// round 15
// speedup vs baseline: 1.2570x; 1.2570x over previous
#include <cuda_runtime.h>
#include <math.h>

// Problem constants
#define WINDOW 40
#define E 8
#define FDIM 64
#define TDIM 64
#define KERNEL 5
#define IN_CH 144          // F + 10*E
#define LIN_IN 36          // WINDOW + 1 - KERNEL
#define NCOL 320           // WINDOW * E rank columns
#define NMAX 8192

// Scratch (device globals — no allocation allowed)
__device__ float g_cols[(size_t)NCOL * NMAX];   // [col][n] gathered last-window values
__device__ float g_rankT[(size_t)NCOL * NMAX];  // [col][n] rank/N (coalesced writes)
__device__ float g_rank[(size_t)NMAX * NCOL];   // [n][col] rank/N (coalesced main reads)

// ---------------------------------------------------------------------------
// Kernel 1: gather x[:, 24+t, 0:8] -> g_cols[(t*8+f)][n]  (proven ~12us)
// ---------------------------------------------------------------------------
__global__ void gather_kernel(const float* __restrict__ x, int N) {
    __shared__ float tile[256][9];   // pad 9 -> conflict-free both phases
    const int t  = blockIdx.y;
    const int n0 = blockIdx.x * 256;
    const int tid = threadIdx.x;
    const int n = n0 + tid;
    if (n < N) {
        const float4* p = (const float4*)(x + (size_t)n * (TDIM * FDIM) + (24 + t) * FDIM);
        float4 a = p[0], b = p[1];
        tile[tid][0] = a.x; tile[tid][1] = a.y; tile[tid][2] = a.z; tile[tid][3] = a.w;
        tile[tid][4] = b.x; tile[tid][5] = b.y; tile[tid][6] = b.z; tile[tid][7] = b.w;
    }
    __syncthreads();
    #pragma unroll
    for (int idx = tid; idx < 8 * 256; idx += 256) {
        int f = idx >> 8, s = idx & 255;
        int nn = n0 + s;
        if (nn < N) g_cols[(size_t)(t * 8 + f) * NMAX + nn] = tile[s][f];
    }
}

// ---------------------------------------------------------------------------
// Kernel 2: exact stable descending rank.
// 15-bit bucket histogram -> conflict-free scan -> scatter of PACKED
// (key_low17<<13 | index) words into sorted-grouped array -> rank =
// bucket_start + #{packed smaller}. Packed integer compare == lexicographic
// (key, index): bit-exact vs stable argsort(argsort(-last)).
// smem 96KB -> 2 blocks/SM; compare loop = 1 independent LDS/iter.
// ---------------------------------------------------------------------------
#define RT 512
#define NBIN 32768                 // 15-bit buckets of the ascending key
#define HWORDS (NBIN / 2)          // 16384 u16-pair words
__device__ __forceinline__ int hphys(unsigned int L) {
    return (int)(((L & 31u) << 9) | (L >> 5));   // bijection on [0,16384), scan = stride-512
}

// dynamic smem: packed u32[8192] (32KB) | hist u32[16384] (64KB) = 98304 B
#define OFF_HIST 32768
#define RANK_SMEM (OFF_HIST + HWORDS * 4)

__device__ __forceinline__ unsigned int key_of(float f) {
    unsigned int u = __float_as_uint(f);
    unsigned int mono = u ^ ((u >> 31) ? 0xFFFFFFFFu : 0x80000000u);
    return ~mono;                   // ascending key == descending value
}

__global__ __launch_bounds__(RT) void rank_kernel(int N) {
    extern __shared__ unsigned char sm_raw[];
    unsigned int* packed = (unsigned int*)sm_raw;              // sorted-grouped packed words
    unsigned int* hist   = (unsigned int*)(sm_raw + OFF_HIST); // u16-pair counts -> cursors
    __shared__ unsigned int aux2[16];

    const int c    = blockIdx.x;
    const int tid  = threadIdx.x;
    const int lane = tid & 31, wrp = tid >> 5;
    const float* col = &g_cols[(size_t)c * NMAX];

    for (int i = tid; i < HWORDS; i += RT) hist[i] = 0u;
    __syncthreads();

    // ---- pass A: histogram (coalesced loads; g_cols is L2-resident) ----
    for (int i = tid; i < N; i += RT) {
        unsigned int k = key_of(col[i]);
        unsigned int b = k >> 17;               // top 15 bits
        atomicAdd(&hist[hphys(b >> 1)], 1u << ((b & 1) * 16));
    }
    __syncthreads();

    // ---- exclusive scan over 32768 bins; thread owns logical words tid*32..+31,
    //      physical w*512+tid -> conflict-free, no padding ----
    unsigned int tsum = 0;
    #pragma unroll
    for (int w = 0; w < 32; ++w) {
        unsigned int v = hist[w * 512 + tid];
        tsum += (v & 0xFFFFu) + (v >> 16);
    }
    unsigned int v = tsum;
    #pragma unroll
    for (int d = 1; d < 32; d <<= 1) {
        unsigned int t2 = __shfl_up_sync(0xFFFFFFFFu, v, d);
        if (lane >= d) v += t2;
    }
    if (lane == 31) aux2[wrp] = v;
    __syncthreads();
    if (wrp == 0 && lane < 16) {
        unsigned int s = aux2[lane];
        #pragma unroll
        for (int d = 1; d < 16; d <<= 1) {
            unsigned int t2 = __shfl_up_sync(0x0000FFFFu, s, d);
            if (lane >= d) s += t2;
        }
        aux2[lane] = s;
    }
    __syncthreads();
    unsigned int run = v - tsum + (wrp ? aux2[wrp - 1] : 0u);  // exclusive prefix
    #pragma unroll
    for (int w = 0; w < 32; ++w) {
        unsigned int pv = hist[w * 512 + tid];
        unsigned int lo = pv & 0xFFFFu, hi = pv >> 16;
        hist[w * 512 + tid] = run | ((run + lo) << 16);   // packed bucket-start cursors
        run += lo + hi;
    }
    __syncthreads();

    // ---- pass B: scatter packed (key_low17<<13 | index) into bucket groups ----
    for (int i = tid; i < N; i += RT) {
        unsigned int k = key_of(col[i]);
        unsigned int b = k >> 17;
        unsigned int sh = (b & 1) * 16;
        unsigned int old = atomicAdd(&hist[hphys(b >> 1)], 1u << sh);
        int pos = (old >> sh) & 0xFFFF;
        packed[pos] = ((k & 0x1FFFFu) << 13) | (unsigned int)i;
    }
    __syncthreads();
    // cursors now hold bucket ENDS: end(b) = start(b+1)

    // ---- rank: bucket_start + count of smaller packed words in bucket ----
    const float inv = 1.0f / (float)N;
    float* dst = &g_rankT[(size_t)c * NMAX];
    for (int i = tid; i < N; i += RT) {
        unsigned int k = key_of(col[i]);
        unsigned int b = k >> 17;
        unsigned int we = hist[hphys(b >> 1)];
        int e = (we >> ((b & 1) * 16)) & 0xFFFF;
        int s = 0;
        if (b) {
            unsigned int b1 = b - 1;
            unsigned int ws2 = hist[hphys(b1 >> 1)];
            s = (ws2 >> ((b1 & 1) * 16)) & 0xFFFF;
        }
        const unsigned int pm = ((k & 0x1FFFFu) << 13) | (unsigned int)i;
        int r = s;
        for (int p = s; p < e; ++p)
            r += (packed[p] < pm);               // 1 independent LDS per iter
        dst[i] = (float)r * inv;                 // coalesced store
    }
}

// ---------------------------------------------------------------------------
// Kernel 3: transpose g_rankT[c][n] -> g_rank[n][c] (both sides coalesced)
// ---------------------------------------------------------------------------
__global__ void transpose_kernel(int N) {
    __shared__ float tile[32][33];
    const int c0 = blockIdx.x * 32;
    const int n0 = blockIdx.y * 32;
    const int tx = threadIdx.x, ty = threadIdx.y;   // 32 x 8
    #pragma unroll
    for (int j = ty; j < 32; j += 8) {
        int n = n0 + tx;
        if (n < N) tile[j][tx] = g_rankT[(size_t)(c0 + j) * NMAX + n];
    }
    __syncthreads();
    #pragma unroll
    for (int j = ty; j < 32; j += 8) {
        int n = n0 + j;
        if (n < N) g_rank[(size_t)n * NCOL + c0 + tx] = tile[tx][j];
    }
}

// ---------------------------------------------------------------------------
// Kernel 4: per-sample stats + channel-127 conv + leaky + linear.
// (R11-proven: __launch_bounds__(320,5), regs 32, occ 86%)
// ---------------------------------------------------------------------------
__global__ __launch_bounds__(320, 5) void main_kernel(
    const float* __restrict__ x, const float* __restrict__ conv_w,
    const float* __restrict__ conv_b, const float* __restrict__ lin_w,
    const float* __restrict__ lin_b, float* __restrict__ out, int N)
{
    __shared__ float xe[59 * 8];          // rows 5..63 of first 8 features
    __shared__ float xc[WINDOW * IN_CH];  // assembled conv input [40][144]
    __shared__ float ws[IN_CH * KERNEL];  // conv_w[127]
    __shared__ float lw[LIN_IN];
    __shared__ float part[LIN_IN];
    __shared__ float part2[36 * 37];      // [t][chunk j], padded stride 37

    const int n   = blockIdx.x;
    const int tid = threadIdx.x;
    const float* xn = x + (size_t)n * (TDIM * FDIM);

    // ---- phase 1: loads ----
    for (int i = tid; i < IN_CH * KERNEL; i += 320) ws[i] = conv_w[127 * IN_CH * KERNEL + i];
    if (tid < LIN_IN) lw[tid] = lin_w[tid];

    for (int i = tid; i < 59 * 8; i += 320) {
        int r = i >> 3, f = i & 7;
        xe[i] = xn[(5 + r) * FDIM + f];
    }
    {   // raw channels: x[n, 24:64, 0:64] is 2560 contiguous floats
        const float4* src = (const float4*)(xn + 24 * FDIM);
        for (int q = tid; q < 640; q += 320) {
            float4 v = src[q];
            int l = q * 4;
            int t = l >> 6, i = l & 63;
            *(float4*)&xc[t * IN_CH + i] = v;
        }
    }
    {   // rank: coalesced 1280B block read; feeds week (80..87) and month (120..127)
        float r = __ldg(&g_rank[(size_t)n * NCOL + tid]);
        int t = tid >> 3, f = tid & 7;
        xc[t * IN_CH + 80 + f]  = r;
        xc[t * IN_CH + 120 + f] = r;
    }
    __syncthreads();

    // ---- phase 2: sliding-window stats (thread = one (t,f) pair) ----
    {
        const int t = tid >> 3, f = tid & 7;
        float* row = &xc[t * IN_CH];
        float s = 0.f, s2 = 0.f, mx = -1e30f, mn = 1e30f;
        #pragma unroll
        for (int j = 0; j < 5; ++j) {
            float v = xe[(15 + t + j) * 8 + f];
            s += v; s2 = fmaf(v, v, s2);
            mx = fmaxf(mx, v); mn = fminf(mn, v);
        }
        row[64 + f] = s * 0.2f;
        row[72 + f] = sqrtf(fmaxf((s2 - s * s * 0.2f) * 0.25f, 0.f));
        row[88 + f] = mx;
        row[96 + f] = mn;
        s = 0.f; s2 = 0.f; mx = -1e30f; mn = 1e30f;
        #pragma unroll
        for (int j = 0; j < 20; ++j) {
            float v = xe[(t + j) * 8 + f];
            s += v; s2 = fmaf(v, v, s2);
            mx = fmaxf(mx, v); mn = fminf(mn, v);
        }
        row[104 + f] = s * 0.05f;
        row[112 + f] = sqrtf(fmaxf((s2 - s * s * 0.05f) * (1.0f / 19.0f), 0.f));
        row[128 + f] = mx;
        row[136 + f] = mn;
    }
    __syncthreads();

    // ---- phase 3: conv ch-127 via sliding accumulation ----
    // 144 threads: q = t-range quarter (9 outputs), j = float4 channel chunk.
    if (tid < 144) {
        const int q = tid / 36, j = tid - q * 36;
        float4 w4[KERNEL];
        #pragma unroll
        for (int k = 0; k < KERNEL; ++k) {
            w4[k].x = ws[(4 * j + 0) * KERNEL + k];
            w4[k].y = ws[(4 * j + 1) * KERNEL + k];
            w4[k].z = ws[(4 * j + 2) * KERNEL + k];
            w4[k].w = ws[(4 * j + 3) * KERNEL + k];
        }
        float acc[9];
        #pragma unroll
        for (int a = 0; a < 9; ++a) acc[a] = 0.f;
        const float4* xc4 = (const float4*)xc;
        const int r0 = 9 * q;
        #pragma unroll
        for (int rr = 0; rr < 13; ++rr) {
            float4 vv = xc4[(r0 + rr) * 36 + j];
            #pragma unroll
            for (int k = 0; k < KERNEL; ++k) {
                const int tt = rr - k;
                if (tt >= 0 && tt <= 8) {
                    acc[tt] = fmaf(w4[k].x, vv.x, acc[tt]);
                    acc[tt] = fmaf(w4[k].y, vv.y, acc[tt]);
                    acc[tt] = fmaf(w4[k].z, vv.z, acc[tt]);
                    acc[tt] = fmaf(w4[k].w, vv.w, acc[tt]);
                }
            }
        }
        #pragma unroll
        for (int a = 0; a < 9; ++a) part2[(r0 + a) * 37 + j] = acc[a];
    }
    __syncthreads();

    if (tid < LIN_IN) {
        float s = 0.f;
        #pragma unroll
        for (int j2 = 0; j2 < 36; ++j2) s += part2[tid * 37 + j2];
        s += conv_b[127];
        s = (s >= 0.0f) ? s : 0.01f * s;   // leaky ALPHA=0.01
        part[tid] = s * lw[tid];
    }
    __syncthreads();
    if (tid < 32) {
        float v = part[tid] + ((tid < 4) ? part[32 + tid] : 0.0f);
        #pragma unroll
        for (int d = 16; d > 0; d >>= 1)
            v += __shfl_down_sync(0xFFFFFFFFu, v, d);
        if (tid == 0) out[n] = v + lin_b[0];
    }
}

// ---------------------------------------------------------------------------
extern "C" void kernel_launch(void* const* d_in, const int* in_sizes, int n_in,
                              void* d_out, int out_size) {
    const float* x      = (const float*)d_in[0];
    const float* conv_w = (const float*)d_in[1];
    const float* conv_b = (const float*)d_in[2];
    const float* lin_w  = (const float*)d_in[3];
    const float* lin_b  = (const float*)d_in[4];
    float* out = (float*)d_out;
    const int N = in_sizes[0] / (TDIM * FDIM);   // 8000

    cudaFuncSetAttribute(rank_kernel, cudaFuncAttributeMaxDynamicSharedMemorySize, RANK_SMEM);

    dim3 gg((N + 255) / 256, WINDOW);
    gather_kernel<<<gg, 256>>>(x, N);
    rank_kernel<<<NCOL, RT, RANK_SMEM>>>(N);
    dim3 tb(32, 8);
    dim3 tg(NCOL / 32, (N + 31) / 32);
    transpose_kernel<<<tg, tb>>>(N);
    main_kernel<<<N, 320>>>(x, conv_w, conv_b, lin_w, lin_b, out, N);
}